// round 2
// baseline (speedup 1.0000x reference)
#include <cuda_runtime.h>

#define FULL 0xFFFFFFFFu

constexpr int B  = 16;
constexpr int T  = 512;
constexpr int C  = 3;
constexpr int V  = 16;
constexpr int H  = 128;
constexpr int NC = 12;

constexpr int POS_PER_B    = T * V;          // 8192
constexpr int CHUNKS       = 64;             // blocks per batch element
constexpr int POS_PER_BLK  = POS_PER_B / CHUNKS;  // 128
constexpr int NWARPS       = 8;
constexpr int THREADS      = NWARPS * 32;

// shared layout (in floats)
constexpr int W2C_STRIDE = 132;                       // padded column stride (16B-aligned, conflict-free)
constexpr int SM_W2C  = 0;                            // [128 cols][132]
constexpr int SM_W1   = SM_W2C + H * W2C_STRIDE;      // [3][128]  folded w1
constexpr int SM_C1   = SM_W1 + 3 * H;                // [128]
constexpr int SM_C2   = SM_C1 + H;                    // [128]
constexpr int SM_INV2 = SM_C2 + H;                    // [128]
constexpr int SM_SACC = SM_INV2 + H;                  // [128]
constexpr int SM_TOTAL_F = SM_SACC + H;
constexpr int SM_BYTES = SM_TOTAL_F * 4;              // ~71 KB -> dynamic smem

__device__ float g_cnt[B * H];   // spike-count accumulator (scratch; zeroed per launch)

__global__ void snn_zero() {
    int i = blockIdx.x * blockDim.x + threadIdx.x;
    if (i < B * H) g_cnt[i] = 0.f;
}

// sparse column accumulation: add W2' columns selected by 4 group masks into (X,Y,Z,W)
__device__ __forceinline__ void acc4(const float* __restrict__ colb,
                                     unsigned mm0, unsigned mm1, unsigned mm2, unsigned mm3,
                                     float& X, float& Y, float& Z, float& W) {
    unsigned mm[4] = {mm0, mm1, mm2, mm3};
#pragma unroll
    for (int g = 0; g < 4; g++) {
        unsigned m = mm[g];
        while (m) {                       // uniform across warp (ballot result)
            int bit = __ffs(m) - 1;
            m &= m - 1;
            const float4 cv = *reinterpret_cast<const float4*>(colb + (g * 32 + bit) * W2C_STRIDE);
            X += cv.x; Y += cv.y; Z += cv.z; W += cv.w;
        }
    }
}

// LIF2 over 4 steps with inputs h2_1..h2_4 reconstructed from A,B1,B2,B3; returns spike count
__device__ __forceinline__ float lif2(float A, float Bb1, float Bb2, float Bb3, float cc) {
    float base = A + cc;
    float vv = base * 0.5f;               // step 1: v = 0 + (h-0)/2
    float cnt = 0.f;
    if (vv >= 0.5f) { cnt += 1.f; vv = 0.f; }
    float h = base + Bb3;                 // step 2
    vv = vv + (h - vv) * 0.5f;
    if (vv >= 0.5f) { cnt += 1.f; vv = 0.f; }
    h = base + Bb2;                       // step 3
    vv = vv + (h - vv) * 0.5f;
    if (vv >= 0.5f) { cnt += 1.f; vv = 0.f; }
    h = base + Bb3 + Bb1;                 // step 4
    vv = vv + (h - vv) * 0.5f;
    if (vv >= 0.5f) cnt += 1.f;
    return cnt;
}

__global__ void snn_main(const float* __restrict__ x,
                         const float* __restrict__ w1, const float* __restrict__ b1,
                         const float* __restrict__ g1, const float* __restrict__ be1,
                         const float* __restrict__ m1, const float* __restrict__ rv1,
                         const float* __restrict__ w2, const float* __restrict__ b2,
                         const float* __restrict__ g2, const float* __restrict__ be2,
                         const float* __restrict__ m2, const float* __restrict__ rv2) {
    extern __shared__ float sm[];
    const int tid = threadIdx.x;

    // ---- fold BN into weights/biases ----
    if (tid < H) {
        float inv1 = g1[tid] * rsqrtf(rv1[tid] + 1e-5f);
        sm[SM_C1 + tid]        = (b1[tid] - m1[tid]) * inv1 + be1[tid];
        sm[SM_W1 + 0 * H + tid] = w1[tid * 3 + 0] * inv1;
        sm[SM_W1 + 1 * H + tid] = w1[tid * 3 + 1] * inv1;
        sm[SM_W1 + 2 * H + tid] = w1[tid * 3 + 2] * inv1;
        float inv2 = g2[tid] * rsqrtf(rv2[tid] + 1e-5f);
        sm[SM_INV2 + tid] = inv2;
        sm[SM_C2 + tid]   = (b2[tid] - m2[tid]) * inv2 + be2[tid];
        sm[SM_SACC + tid] = 0.f;
    }
    __syncthreads();
    // W2' column-major: w2c[o*132 + p] = w2[p][o] * inv2[p]   (coalesced global read)
    for (int idx = tid; idx < H * H; idx += THREADS) {
        int o = idx & (H - 1), p = idx >> 7;
        sm[SM_W2C + o * W2C_STRIDE + p] = w2[p * H + o] * sm[SM_INV2 + p];
    }
    __syncthreads();

    const int bb    = blockIdx.x / CHUNKS;
    const int chunk = blockIdx.x % CHUNKS;
    const int warp  = tid >> 5, lane = tid & 31;
    const float* xb = x + (size_t)bb * (T * C * V);
    const float* colb = sm + SM_W2C + 4 * lane;   // per-lane float4 offset within columns

    // hoist per-lane folded fc1 params (o = g*32 + lane)
    float w1a[4], w1b[4], w1c[4], c1r[4];
#pragma unroll
    for (int g = 0; g < 4; g++) {
        int o = g * 32 + lane;
        w1a[g] = sm[SM_W1 + 0 * H + o];
        w1b[g] = sm[SM_W1 + 1 * H + o];
        w1c[g] = sm[SM_W1 + 2 * H + o];
        c1r[g] = sm[SM_C1 + o];
    }
    // per-lane c2 for its 4 output rows (p = 4*lane..4*lane+3)
    const float c2x = sm[SM_C2 + 4 * lane + 0];
    const float c2y = sm[SM_C2 + 4 * lane + 1];
    const float c2z = sm[SM_C2 + 4 * lane + 2];
    const float c2w = sm[SM_C2 + 4 * lane + 3];

    float f0 = 0.f, f1 = 0.f, f2 = 0.f, f3 = 0.f;   // spike-count totals (this warp)

    for (int i = warp; i < POS_PER_BLK; i += NWARPS) {
        int pos = chunk * POS_PER_BLK + i;          // in [0, 8192)
        int t = pos >> 4, v = pos & 15;
        const float* xp = xb + t * (C * V) + v;
        float xr = (lane < C) ? xp[lane * V] : 0.f;
        float x0 = __shfl_sync(FULL, xr, 0);
        float x1 = __shfl_sync(FULL, xr, 1);
        float x2 = __shfl_sync(FULL, xr, 2);

        unsigned m4[4], m3[4], m2m[4], m1m[4];
#pragma unroll
        for (int g = 0; g < 4; g++) {
            float h = fmaf(w1a[g], x0, fmaf(w1b[g], x1, fmaf(w1c[g], x2, c1r[g])));
            // LIF1 with constant input: pattern = f(first-spike step)
            int cat;
            float vv = h * 0.5f;
            if (vv >= 0.5f) cat = 4;                              // 1111
            else {
                vv = vv + (h - vv) * 0.5f;
                if (vv >= 0.5f) cat = 3;                          // 0101
                else {
                    vv = vv + (h - vv) * 0.5f;
                    if (vv >= 0.5f) cat = 2;                      // 0010
                    else {
                        vv = vv + (h - vv) * 0.5f;
                        cat = (vv >= 0.5f) ? 1 : 0;               // 0001 / 0000
                    }
                }
            }
            m4[g]  = __ballot_sync(FULL, cat == 4);
            m3[g]  = __ballot_sync(FULL, cat == 3);
            m2m[g] = __ballot_sync(FULL, cat == 2);
            m1m[g] = __ballot_sync(FULL, cat == 1);
        }

        float Ax = 0, Ay = 0, Az = 0, Aw = 0;
        float B3x = 0, B3y = 0, B3z = 0, B3w = 0;
        float B2x = 0, B2y = 0, B2z = 0, B2w = 0;
        float B1x = 0, B1y = 0, B1z = 0, B1w = 0;
        acc4(colb, m4[0],  m4[1],  m4[2],  m4[3],  Ax,  Ay,  Az,  Aw);
        acc4(colb, m3[0],  m3[1],  m3[2],  m3[3],  B3x, B3y, B3z, B3w);
        acc4(colb, m2m[0], m2m[1], m2m[2], m2m[3], B2x, B2y, B2z, B2w);
        acc4(colb, m1m[0], m1m[1], m1m[2], m1m[3], B1x, B1y, B1z, B1w);

        f0 += lif2(Ax, B1x, B2x, B3x, c2x);
        f1 += lif2(Ay, B1y, B2y, B3y, c2y);
        f2 += lif2(Az, B1z, B2z, B3z, c2z);
        f3 += lif2(Aw, B1w, B2w, B3w, c2w);
    }

    // warp totals -> shared -> global (lane l owns rows 4l..4l+3 consistently)
    atomicAdd(&sm[SM_SACC + 4 * lane + 0], f0);
    atomicAdd(&sm[SM_SACC + 4 * lane + 1], f1);
    atomicAdd(&sm[SM_SACC + 4 * lane + 2], f2);
    atomicAdd(&sm[SM_SACC + 4 * lane + 3], f3);
    __syncthreads();
    if (tid < H) atomicAdd(&g_cnt[bb * H + tid], sm[SM_SACC + tid]);
}

__global__ void snn_final(const float* __restrict__ wc, const float* __restrict__ bc,
                          float* __restrict__ out) {
    __shared__ float feat[B * H];
    int tid = threadIdx.x;
    for (int i = tid; i < B * H; i += blockDim.x)
        feat[i] = g_cnt[i] * (1.f / (4.f * (float)POS_PER_B));
    __syncthreads();
    if (tid < B * NC) {
        int b = tid / NC, n = tid % NC;
        float s = bc[n];
#pragma unroll 8
        for (int p = 0; p < H; p++)
            s = fmaf(wc[n * H + p], feat[b * H + p], s);
        out[tid] = s;
    }
}

extern "C" void kernel_launch(void* const* d_in, const int* in_sizes, int n_in,
                              void* d_out, int out_size) {
    const float* x   = (const float*)d_in[0];
    const float* w1  = (const float*)d_in[1];
    const float* b1  = (const float*)d_in[2];
    const float* g1  = (const float*)d_in[3];
    const float* be1 = (const float*)d_in[4];
    const float* m1  = (const float*)d_in[5];
    const float* rv1 = (const float*)d_in[6];
    const float* w2  = (const float*)d_in[7];
    const float* b2  = (const float*)d_in[8];
    const float* g2  = (const float*)d_in[9];
    const float* be2 = (const float*)d_in[10];
    const float* m2  = (const float*)d_in[11];
    const float* rv2 = (const float*)d_in[12];
    const float* wc  = (const float*)d_in[13];
    const float* bc  = (const float*)d_in[14];

    cudaFuncSetAttribute(snn_main, cudaFuncAttributeMaxDynamicSharedMemorySize, SM_BYTES);

    snn_zero<<<(B * H + 255) / 256, 256>>>();   // R1 fix: zero ALL B*H elements every call
    snn_main<<<B * CHUNKS, THREADS, SM_BYTES>>>(x, w1, b1, g1, be1, m1, rv1,
                                                w2, b2, g2, be2, m2, rv2);
    snn_final<<<1, 256>>>(wc, bc, (float*)d_out);
}

// round 3
// speedup vs baseline: 1.1705x; 1.1705x over previous
#include <cuda_runtime.h>

#define FULL 0xFFFFFFFFu

constexpr int B  = 16;
constexpr int T  = 512;
constexpr int C  = 3;
constexpr int V  = 16;
constexpr int H  = 128;
constexpr int NC = 12;

constexpr int NWARPS   = 8;
constexpr int THREADS  = NWARPS * 32;
constexpr int BLK_PER_B = 27;
constexpr int NBLK      = B * BLK_PER_B;          // 432 blocks = one wave at 3/SM
constexpr int TOTAL_WARPS = NBLK * NWARPS;        // 3456

// shared layout (floats)
constexpr int W2C_STRIDE = 132;                   // 16B-aligned col stride, conflict-free gathers
constexpr int SM_W2C  = 0;                        // [128 cols][132]
constexpr int SM_C2   = SM_W2C + H * W2C_STRIDE;  // [128]
constexpr int SM_INV2 = SM_C2 + H;                // [128]
constexpr int SM_SACC = SM_INV2 + H;              // [128]
constexpr int SM_TOT  = SM_SACC + H;
constexpr int SM_BYTES = SM_TOT * 4;              // ~69 KB -> 3 blocks/SM

__device__ float g_part[NBLK * H];                // per-block spike-count partials (exact ints)

// packed f32x2 helpers
__device__ __forceinline__ void addx2(unsigned long long& acc, unsigned long long v) {
    asm("add.rn.f32x2 %0, %0, %1;" : "+l"(acc) : "l"(v));
}
__device__ __forceinline__ void unpk(unsigned long long v, float& lo, float& hi) {
    asm("mov.b64 {%0, %1}, %2;" : "=f"(lo), "=f"(hi) : "l"(v));
}

// accumulate selected W2' columns (mask m, group g) into two packed accumulators
__device__ __forceinline__ void accm(const float* __restrict__ colb, int g, unsigned m,
                                     unsigned long long& xy, unsigned long long& zw) {
    while (m) {                                   // warp-uniform (ballot result)
        int bit = __ffs(m) - 1;
        m &= m - 1;
        const ulonglong2 cv =
            *reinterpret_cast<const ulonglong2*>(colb + (g * 32 + bit) * W2C_STRIDE);
        addx2(xy, cv.x);
        addx2(zw, cv.y);
    }
}

// LIF2 over 4 steps; h2 inputs reconstructed from A,B1,B2,B3; returns spike count
__device__ __forceinline__ float lif2(float A, float Bb1, float Bb2, float Bb3, float cc) {
    float base = A + cc;
    float vv = base * 0.5f;
    float cnt = 0.f;
    if (vv >= 0.5f) { cnt += 1.f; vv = 0.f; }
    float h = base + Bb3;
    vv = vv + (h - vv) * 0.5f;
    if (vv >= 0.5f) { cnt += 1.f; vv = 0.f; }
    h = base + Bb2;
    vv = vv + (h - vv) * 0.5f;
    if (vv >= 0.5f) { cnt += 1.f; vv = 0.f; }
    h = base + Bb3 + Bb1;
    vv = vv + (h - vv) * 0.5f;
    if (vv >= 0.5f) cnt += 1.f;
    return cnt;
}

__global__ void __launch_bounds__(THREADS, 3)
snn_main(const float* __restrict__ x,
         const float* __restrict__ w1, const float* __restrict__ b1,
         const float* __restrict__ g1, const float* __restrict__ be1,
         const float* __restrict__ m1, const float* __restrict__ rv1,
         const float* __restrict__ w2, const float* __restrict__ b2,
         const float* __restrict__ g2, const float* __restrict__ be2,
         const float* __restrict__ m2, const float* __restrict__ rv2) {
    extern __shared__ float sm[];
    const int tid  = threadIdx.x;
    const int warp = tid >> 5, lane = tid & 31;

    // ---- fold BN2 into W2 (column-major, scaled) + c2; zero SACC ----
    if (tid < H) {
        float inv2 = g2[tid] * rsqrtf(rv2[tid] + 1e-5f);
        sm[SM_INV2 + tid] = inv2;
        sm[SM_C2 + tid]   = (b2[tid] - m2[tid]) * inv2 + be2[tid];
        sm[SM_SACC + tid] = 0.f;
    }
    __syncthreads();
    for (int idx = tid; idx < H * H; idx += THREADS) {
        int o = idx & (H - 1), p = idx >> 7;      // coalesced global read
        sm[SM_W2C + o * W2C_STRIDE + p] = w2[p * H + o] * sm[SM_INV2 + p];
    }
    __syncthreads();

    // ---- per-thread folded fc1 params (channel o = g*32 + lane) ----
    float w1a[4], w1b[4], w1c[4], c1r[4];
#pragma unroll
    for (int g = 0; g < 4; g++) {
        int o = g * 32 + lane;
        float inv1 = g1[o] * rsqrtf(rv1[o] + 1e-5f);
        w1a[g] = w1[o * 3 + 0] * inv1;
        w1b[g] = w1[o * 3 + 1] * inv1;
        w1c[g] = w1[o * 3 + 2] * inv1;
        c1r[g] = (b1[o] - m1[o]) * inv1 + be1[o];
    }
    const float c2x = sm[SM_C2 + 4 * lane + 0];
    const float c2y = sm[SM_C2 + 4 * lane + 1];
    const float c2z = sm[SM_C2 + 4 * lane + 2];
    const float c2w = sm[SM_C2 + 4 * lane + 3];
    const float* colb = sm + SM_W2C + 4 * lane;

    // ---- uniform position span for this warp (never crosses batch boundary) ----
    const int wgid = blockIdx.x * NWARPS + warp;
    int p  = (wgid * 1024) / BLK_PER_B;           // = wgid * 131072 / 3456
    int ep = ((wgid + 1) * 1024) / BLK_PER_B;

    float f0 = 0.f, f1 = 0.f, f2 = 0.f, f3 = 0.f;

    while (p < ep) {
        int row = p >> 4;                         // global (b,t) row: 48 contiguous floats
        const float* rp = x + row * (C * V);
        float ld0 = rp[lane];                     // lanes 0-15: c0[v], 16-31: c1[v]
        float ld1 = (lane < 16) ? rp[32 + lane] : 0.f;   // c2[v]
        int ve = min(16, ep - (row << 4));

        for (int v = p - (row << 4); v < ve; v++) {
            float x0 = __shfl_sync(FULL, ld0, v);
            float x1 = __shfl_sync(FULL, ld0, v + 16);
            float x2 = __shfl_sync(FULL, ld1, v);

            unsigned long long Axy = 0, Azw = 0, B1xy = 0, B1zw = 0,
                               B2xy = 0, B2zw = 0, B3xy = 0, B3zw = 0;
#pragma unroll
            for (int g = 0; g < 4; g++) {
                float h = fmaf(w1a[g], x0, fmaf(w1b[g], x1, fmaf(w1c[g], x2, c1r[g])));
                // LIF1 with constant input: category = first-spike step
                int cat;
                float vv = h * 0.5f;
                if (vv >= 0.5f) cat = 4;                          // 1111
                else {
                    vv = vv + (h - vv) * 0.5f;
                    if (vv >= 0.5f) cat = 3;                      // 0101
                    else {
                        vv = vv + (h - vv) * 0.5f;
                        if (vv >= 0.5f) cat = 2;                  // 0010
                        else {
                            vv = vv + (h - vv) * 0.5f;
                            cat = (vv >= 0.5f) ? 1 : 0;           // 0001 / 0000
                        }
                    }
                }
                unsigned m;
                m = __ballot_sync(FULL, cat == 4); accm(colb, g, m, Axy,  Azw);
                m = __ballot_sync(FULL, cat == 3); accm(colb, g, m, B3xy, B3zw);
                m = __ballot_sync(FULL, cat == 2); accm(colb, g, m, B2xy, B2zw);
                m = __ballot_sync(FULL, cat == 1); accm(colb, g, m, B1xy, B1zw);
            }

            float Ax, Ay, Az, Aw, B1x, B1y, B1z, B1w;
            float B2x, B2y, B2z, B2w, B3x, B3y, B3z, B3w;
            unpk(Axy, Ax, Ay);   unpk(Azw, Az, Aw);
            unpk(B1xy, B1x, B1y); unpk(B1zw, B1z, B1w);
            unpk(B2xy, B2x, B2y); unpk(B2zw, B2z, B2w);
            unpk(B3xy, B3x, B3y); unpk(B3zw, B3z, B3w);

            f0 += lif2(Ax, B1x, B2x, B3x, c2x);
            f1 += lif2(Ay, B1y, B2y, B3y, c2y);
            f2 += lif2(Az, B1z, B2z, B3z, c2z);
            f3 += lif2(Aw, B1w, B2w, B3w, c2w);
        }
        p = (row << 4) + ve;
    }

    // counts are small integers -> fp32-exact, order-independent (deterministic)
    atomicAdd(&sm[SM_SACC + 4 * lane + 0], f0);
    atomicAdd(&sm[SM_SACC + 4 * lane + 1], f1);
    atomicAdd(&sm[SM_SACC + 4 * lane + 2], f2);
    atomicAdd(&sm[SM_SACC + 4 * lane + 3], f3);
    __syncthreads();
    if (tid < H) g_part[blockIdx.x * H + tid] = sm[SM_SACC + tid];
}

__global__ void snn_final(const float* __restrict__ wc, const float* __restrict__ bc,
                          float* __restrict__ out) {
    __shared__ float feat[B * H];
    int tid = threadIdx.x;
    for (int i = tid; i < B * H; i += 256) {
        int b = i >> 7, ch = i & (H - 1);
        float s = 0.f;
#pragma unroll
        for (int k = 0; k < BLK_PER_B; k++)
            s += g_part[(b * BLK_PER_B + k) * H + ch];
        feat[i] = s * (1.f / (4.f * (float)(T * V)));
    }
    __syncthreads();
    if (tid < B * NC) {
        int b = tid / NC, n = tid % NC;
        float s = bc[n];
#pragma unroll 8
        for (int pch = 0; pch < H; pch++)
            s = fmaf(wc[n * H + pch], feat[b * H + pch], s);
        out[tid] = s;
    }
}

extern "C" void kernel_launch(void* const* d_in, const int* in_sizes, int n_in,
                              void* d_out, int out_size) {
    const float* x   = (const float*)d_in[0];
    const float* w1  = (const float*)d_in[1];
    const float* b1  = (const float*)d_in[2];
    const float* g1  = (const float*)d_in[3];
    const float* be1 = (const float*)d_in[4];
    const float* m1  = (const float*)d_in[5];
    const float* rv1 = (const float*)d_in[6];
    const float* w2  = (const float*)d_in[7];
    const float* b2  = (const float*)d_in[8];
    const float* g2  = (const float*)d_in[9];
    const float* be2 = (const float*)d_in[10];
    const float* m2  = (const float*)d_in[11];
    const float* rv2 = (const float*)d_in[12];
    const float* wc  = (const float*)d_in[13];
    const float* bc  = (const float*)d_in[14];

    cudaFuncSetAttribute(snn_main, cudaFuncAttributeMaxDynamicSharedMemorySize, SM_BYTES);

    snn_main<<<NBLK, THREADS, SM_BYTES>>>(x, w1, b1, g1, be1, m1, rv1,
                                          w2, b2, g2, be2, m2, rv2);
    snn_final<<<1, 256>>>(wc, bc, (float*)d_out);
}